// round 13
// speedup vs baseline: 8.1395x; 1.0635x over previous
#include <cuda_runtime.h>
#include <cuda_bf16.h>
#include <math.h>
#include <stdint.h>

#define NATOMS 4096
#define HDIM   128
#define BATCH  128
#define NHEAD  4
#define DHEAD  32
#define H3     384
#define FPAD   288
#define KSPLIT 8

// -------- scratch (no allocations allowed) --------
__device__ float g_scratch[8300000];
__device__ int   g_bidx[NATOMS];

// ---------------- helpers ----------------
__device__ __forceinline__ float silu_f(float x) {
    return x / (1.f + __expf(-x));
}
__device__ __forceinline__ void ldsm4(uint32_t& r0, uint32_t& r1, uint32_t& r2, uint32_t& r3, uint32_t addr) {
    asm volatile("ldmatrix.sync.aligned.m8n8.x4.shared.b16 {%0,%1,%2,%3}, [%4];"
                 : "=r"(r0), "=r"(r1), "=r"(r2), "=r"(r3) : "r"(addr));
}
__device__ __forceinline__ void ldsm4t(uint32_t& r0, uint32_t& r1, uint32_t& r2, uint32_t& r3, uint32_t addr) {
    asm volatile("ldmatrix.sync.aligned.m8n8.x4.trans.shared.b16 {%0,%1,%2,%3}, [%4];"
                 : "=r"(r0), "=r"(r1), "=r"(r2), "=r"(r3) : "r"(addr));
}
__device__ __forceinline__ void mma16816(float* d, const uint32_t* a, uint32_t b0, uint32_t b1) {
    asm volatile("mma.sync.aligned.m16n8k16.row.col.f32.bf16.bf16.f32 "
                 "{%0,%1,%2,%3}, {%4,%5,%6,%7}, {%8,%9}, {%0,%1,%2,%3};"
                 : "+f"(d[0]), "+f"(d[1]), "+f"(d[2]), "+f"(d[3])
                 : "r"(a[0]), "r"(a[1]), "r"(a[2]), "r"(a[3]), "r"(b0), "r"(b1));
}
__device__ __forceinline__ void mma16832(float* d, const uint32_t* a, uint32_t b0, uint32_t b1) {
    asm volatile("mma.sync.aligned.m16n8k32.row.col.f32.e4m3.e4m3.f32 "
                 "{%0,%1,%2,%3}, {%4,%5,%6,%7}, {%8,%9}, {%0,%1,%2,%3};"
                 : "+f"(d[0]), "+f"(d[1]), "+f"(d[2]), "+f"(d[3])
                 : "r"(a[0]), "r"(a[1]), "r"(a[2]), "r"(a[3]), "r"(b0), "r"(b1));
}
__device__ __forceinline__ uint32_t packbf(float lo, float hi) {
    uint32_t r;
    asm volatile("cvt.rn.bf16x2.f32 %0, %1, %2;" : "=r"(r) : "f"(hi), "f"(lo));
    return r;
}
__device__ __forceinline__ uint16_t packe4(float lo, float hi) {
    uint16_t r;
    asm volatile("cvt.rn.satfinite.e4m3x2.f32 %0, %1, %2;" : "=h"(r) : "f"(hi), "f"(lo));
    return r;
}
__device__ __forceinline__ void cpa16(uint32_t dst, const void* src) {
    asm volatile("cp.async.ca.shared.global [%0], [%1], 16;" :: "r"(dst), "l"(src));
}
__device__ __forceinline__ void cpa4(uint32_t dst, const void* src) {
    asm volatile("cp.async.ca.shared.global [%0], [%1], 4;" :: "r"(dst), "l"(src));
}
__device__ __forceinline__ void barh(int id) {
    asm volatile("bar.sync %0, 256;" :: "r"(id) : "memory");
}
__device__ __forceinline__ uint32_t schexp(float x) {
    int i;
    asm("cvt.rni.s32.f32 %0, %1;" : "=r"(i) : "f"(fmaf(x, 8388608.f, 1064876800.f)));
    return (uint32_t)i;
}
__device__ __forceinline__ uint32_t prmt16(uint32_t a, uint32_t b) {
    uint32_t r;
    asm("prmt.b32 %0,%1,%2,0x7632;" : "=r"(r) : "r"(a), "r"(b));
    return r;
}

// ================= fused setup kernel =================
__global__ void __launch_bounds__(256) setup_k(
    const int* __restrict__ elems, const float* __restrict__ emb,
    const float* __restrict__ ln_in_g, const float* __restrict__ ln_in_b,
    __nv_bfloat16* __restrict__ xo,
    const float* __restrict__ aiw, const float* __restrict__ aow,
    const float* __restrict__ opw1, const float* __restrict__ rw1,
    const float* __restrict__ rw2,
    __nv_bfloat16* __restrict__ wqkv, __nv_bfloat16* __restrict__ wao,
    __nv_bfloat16* __restrict__ wop1, __nv_bfloat16* __restrict__ wr1,
    __nv_bfloat16* __restrict__ wr2,
    const float* __restrict__ cell,
    const float* __restrict__ cw1, const float* __restrict__ cb1,
    const float* __restrict__ cw2, const float* __restrict__ cb2,
    float* __restrict__ cf,
    const int* __restrict__ num_atoms,
    float* __restrict__ bmin, float* __restrict__ bmax)
{
    const int b = blockIdx.x, tid = threadIdx.x;

    if (b < 512) {
        int warp = tid >> 5, lane = tid & 31;
        int r = b * 8 + warp;
        int e = elems[r];
        float4 v = *(const float4*)&emb[e * HDIM + lane * 4];
        float s = v.x + v.y + v.z + v.w;
        #pragma unroll
        for (int off = 16; off > 0; off >>= 1) s += __shfl_xor_sync(0xffffffffu, s, off);
        float mean = s * (1.f / 128.f);
        float dx = v.x - mean, dy = v.y - mean, dz = v.z - mean, dw = v.w - mean;
        float sq = dx * dx + dy * dy + dz * dz + dw * dw;
        #pragma unroll
        for (int off = 16; off > 0; off >>= 1) sq += __shfl_xor_sync(0xffffffffu, sq, off);
        float inv = rsqrtf(sq * (1.f / 128.f) + 1e-5f);
        float4 gg = *(const float4*)&ln_in_g[lane * 4];
        float4 bb = *(const float4*)&ln_in_b[lane * 4];
        uint32_t p0 = packbf(dx * inv * gg.x + bb.x, dy * inv * gg.y + bb.y);
        uint32_t p1 = packbf(dz * inv * gg.z + bb.z, dw * inv * gg.w + bb.w);
        *(uint2*)(xo + r * HDIM + lane * 4) = make_uint2(p0, p1);
        return;
    }

    if (b < 1040) {
        int i = (b - 512) * 256 + tid;
        if (i < 49152) wqkv[i] = __float2bfloat16(aiw[i]);
        else if (i < 65536) { int j = i - 49152; wao[j] = __float2bfloat16(aow[j]); }
        else if (i < 102400) {
            int j = i - 65536; int r = j >> 7, c = j & 127;
            wop1[j] = __float2bfloat16(r < 259 ? opw1[r * 128 + c] : 0.f);
        }
        else if (i < 118784) { int j = i - 102400; wr1[j] = __float2bfloat16(rw1[j]); }
        else { int j = i - 118784; wr2[j] = __float2bfloat16(rw2[j]); }
        return;
    }

    if (b < 1048) {
        __shared__ float t1s[16][128];
        int r0 = (b - 1040) * 16;
        #pragma unroll
        for (int i = 0; i < 8; i++) {
            int idx = tid + i * 256;
            int rr = idx >> 7, k = idx & 127;
            int r = r0 + rr;
            float u = cell[r * 3 + 0] * cw1[k] + cell[r * 3 + 1] * cw1[128 + k]
                    + cell[r * 3 + 2] * cw1[256 + k] + cb1[k];
            t1s[rr][k] = silu_f(u);
        }
        __syncthreads();
        int t = tid & 127, half = tid >> 7;
        float acc[8];
        #pragma unroll
        for (int j = 0; j < 8; j++) acc[j] = cb2[t];
        #pragma unroll 4
        for (int k = 0; k < 128; k++) {
            float w = cw2[k * 128 + t];
            #pragma unroll
            for (int j = 0; j < 8; j++) acc[j] += t1s[half * 8 + j][k] * w;
        }
        #pragma unroll
        for (int j = 0; j < 8; j++) cf[(r0 + half * 8 + j) * 128 + t] = acc[j];
        return;
    }

    __shared__ int starts[BATCH + 1];
    if (tid == 0) {
        int acc = 0;
        for (int i = 0; i < BATCH; i++) { starts[i] = acc; acc += num_atoms[i]; }
        starts[BATCH] = acc;
    }
    __syncthreads();
    for (int i = tid; i < NATOMS; i += 256) g_bidx[i] = BATCH - 1;
    __syncthreads();
    if (tid < BATCH) {
        int s = starts[tid], e = starts[tid + 1];
        if (s > NATOMS) s = NATOMS;
        if (e > NATOMS) e = NATOMS;
        for (int i = s; i < e; i++) g_bidx[i] = tid;
        #pragma unroll
        for (int i = 0; i < 3; i++) {
            float a = cell[(3 * tid + i) * 3 + 0];
            float c1 = cell[(3 * tid + i) * 3 + 1];
            float c = cell[(3 * tid + i) * 3 + 2];
            bmin[tid * 3 + i] = fminf(a, fminf(c1, c)) + 1e-6f;
            bmax[tid * 3 + i] = fmaxf(a, fmaxf(c1, c)) - 1e-6f;
        }
    }
}

// ================= QKV GEMM: Q,K -> e4m3 (scaled), V -> bf16 =================
__global__ void __launch_bounds__(128) qkv_k(
    const __nv_bfloat16* __restrict__ A, const __nv_bfloat16* __restrict__ W,
    const float* __restrict__ bias,
    uint8_t* __restrict__ Qf, uint8_t* __restrict__ Kf,
    __nv_bfloat16* __restrict__ Vh)
{
    __shared__ __align__(16) char sA[2 * 32 * 80];
    __shared__ __align__(16) char sW[2 * 32 * 272];
    const int tid = threadIdx.x, lane = tid & 31, warp = tid >> 5;
    const int wr = warp & 1, wc = warp >> 1;
    const int bm = blockIdx.y, nb = blockIdx.x;
    uint32_t aBase = (uint32_t)__cvta_generic_to_shared(sA);
    uint32_t wBase = (uint32_t)__cvta_generic_to_shared(sW);

    #pragma unroll
    for (int p = 0; p < 2; p++) {
        int row = tid >> 2, seg = tid & 3;
        cpa16(aBase + p * 2560 + row * 80 + seg * 16,
              A + (bm * 32 + row) * 128 + p * 32 + seg * 8);
        #pragma unroll
        for (int i = 0; i < 4; i++) {
            int s = tid + i * 128;
            int wrow = s >> 4, wseg = s & 15;
            cpa16(wBase + p * 8704 + wrow * 272 + wseg * 16,
                  W + (p * 32 + wrow) * H3 + nb * 128 + wseg * 8);
        }
        asm volatile("cp.async.commit_group;");
    }

    float acc[8][4];
    #pragma unroll
    for (int j = 0; j < 8; j++)
        #pragma unroll
        for (int c = 0; c < 4; c++) acc[j][c] = 0.f;

    const int i7 = lane & 7, sel = lane >> 3;
    const int arow = wr * 16 + ((sel & 1) ? 8 : 0) + i7;
    const int acol = (sel >> 1) ? 16 : 0;
    const int vrow = ((sel & 1) ? 8 : 0) + i7;
    const int vcol = (sel >= 2) ? 16 : 0;

    for (int ks = 0; ks < 4; ks++) {
        if (ks < 3) asm volatile("cp.async.wait_group 1;");
        else        asm volatile("cp.async.wait_group 0;");
        __syncthreads();
        uint32_t Ab = aBase + (ks & 1) * 2560;
        uint32_t Wb = wBase + (ks & 1) * 8704;
        #pragma unroll
        for (int kh = 0; kh < 2; kh++) {
            uint32_t qa[4];
            ldsm4(qa[0], qa[1], qa[2], qa[3], Ab + arow * 80 + acol + kh * 32);
            #pragma unroll
            for (int j = 0; j < 4; j++) {
                uint32_t r0, r1, r2, r3;
                ldsm4t(r0, r1, r2, r3, Wb + (kh * 16 + vrow) * 272 + wc * 128 + j * 32 + vcol);
                mma16816(acc[2 * j],     qa, r0, r1);
                mma16816(acc[2 * j + 1], qa, r2, r3);
            }
        }
        __syncthreads();
        if (ks + 2 < 4) {
            int p = ks + 2, buf = ks & 1;
            int row = tid >> 2, seg = tid & 3;
            cpa16(aBase + buf * 2560 + row * 80 + seg * 16,
                  A + (bm * 32 + row) * 128 + p * 32 + seg * 8);
            #pragma unroll
            for (int i = 0; i < 4; i++) {
                int s = tid + i * 128;
                int wrow = s >> 4, wseg = s & 15;
                cpa16(wBase + buf * 8704 + wrow * 272 + wseg * 16,
                      W + (p * 32 + wrow) * H3 + nb * 128 + wseg * 8);
            }
            asm volatile("cp.async.commit_group;");
        }
    }

    const int g = lane >> 2, c2 = (lane & 3) * 2;
    int r0 = bm * 32 + wr * 16 + g;
    const float SC = 0.50507248f;
    if (nb < 2) {
        uint8_t* outp = (nb == 0) ? Qf : Kf;
        #pragma unroll
        for (int t = 0; t < 8; t++) {
            int col = wc * 64 + t * 8 + c2;
            float b0v = bias[nb * 128 + col], b1v = bias[nb * 128 + col + 1];
            int h = col >> 5, d = col & 31;
            *(uint16_t*)(outp + (((h << 12) + r0) << 5) + d) =
                packe4((acc[t][0] + b0v) * SC, (acc[t][1] + b1v) * SC);
            *(uint16_t*)(outp + (((h << 12) + r0 + 8) << 5) + d) =
                packe4((acc[t][2] + b0v) * SC, (acc[t][3] + b1v) * SC);
        }
    } else {
        #pragma unroll
        for (int t = 0; t < 8; t++) {
            int col = wc * 64 + t * 8 + c2;
            float b0v = bias[256 + col], b1v = bias[256 + col + 1];
            int h = col >> 5, d = col & 31;
            *(uint32_t*)(Vh + (((h << 12) + r0) << 5) + d) =
                packbf(acc[t][0] + b0v, acc[t][1] + b1v);
            *(uint32_t*)(Vh + (((h << 12) + r0 + 8) << 5) + d) =
                packbf(acc[t][2] + b0v, acc[t][3] + b1v);
        }
    }
}

// ================= fused tail: 512 threads ==========
#define WSTR 272
#define ASTR 592
#define SM_WAO   0
#define SM_WOP1  (128 * WSTR)
#define SM_WR1   (SM_WOP1 + 288 * WSTR)
#define SM_WR2   (SM_WR1 + 128 * WSTR)
#define SM_ACT   (SM_WR2 + 128 * WSTR)
#define SM_STAGE (SM_ACT + 32 * ASTR)
#define SM_PAR   (SM_STAGE + 32 * 136 * 4)
#define PAR_AOBB 0
#define PAR_OPB1 128
#define PAR_RB1  256
#define PAR_RB2  384
#define PAR_LNFG 512
#define PAR_LNFB 772
#define PAR_LN1G 1032
#define PAR_LN1B 1160
#define PAR_RLNG 1288
#define PAR_RLNB 1416
#define PAR_LN2G 1544
#define PAR_LN2B 1672
#define PAR_W3   1800
#define PAR_B3   2184
#define SMEM_TAIL (SM_PAR + 2192 * 4)

__global__ void __launch_bounds__(512) tail_k(
    const float* __restrict__ opart, const float* __restrict__ lpart,
    const __nv_bfloat16* __restrict__ wao, const float* __restrict__ aob_bias,
    const float* __restrict__ lnf_g, const float* __restrict__ lnf_b,
    const float* __restrict__ cf, const float* __restrict__ coordp,
    const int* __restrict__ bidx,
    const __nv_bfloat16* __restrict__ wop1, const float* __restrict__ op_b1,
    const float* __restrict__ ln1_g, const float* __restrict__ ln1_b,
    const __nv_bfloat16* __restrict__ wr1, const float* __restrict__ r_b1,
    const float* __restrict__ rln_g, const float* __restrict__ rln_b,
    const __nv_bfloat16* __restrict__ wr2, const float* __restrict__ r_b2,
    const float* __restrict__ ln2_g, const float* __restrict__ ln2_b,
    const float* __restrict__ w3, const float* __restrict__ b3,
    const float* __restrict__ bmin, const float* __restrict__ bmax,
    float* __restrict__ fout)
{
    extern __shared__ __align__(16) char dsm[];
    const int tid = threadIdx.x, lane = tid & 31, warp = tid >> 5;
    const int hb = warp >> 3;
    const int wc = warp & 7;
    const int bm = blockIdx.x;
    uint32_t base = (uint32_t)__cvta_generic_to_shared(dsm);
    uint32_t aAct = base + SM_ACT + hb * 16 * ASTR;
    float* sSh = (float*)(dsm + SM_STAGE) + hb * 16 * 136;
    const float* par = (const float*)(dsm + SM_PAR);

    #pragma unroll
    for (int i = 0; i < 4; i++) {
        int s = tid + i * 512;
        int row = s >> 4, seg = s & 15;
        cpa16(base + SM_WAO + row * WSTR + seg * 16, wao + row * 128 + seg * 8);
    }
    #pragma unroll
    for (int i = 0; i < 9; i++) {
        int s = tid + i * 512;
        int row = s >> 4, seg = s & 15;
        cpa16(base + SM_WOP1 + row * WSTR + seg * 16, wop1 + row * 128 + seg * 8);
    }
    #pragma unroll
    for (int i = 0; i < 4; i++) {
        int s = tid + i * 512;
        int row = s >> 4, seg = s & 15;
        cpa16(base + SM_WR1 + row * WSTR + seg * 16, wr1 + row * 128 + seg * 8);
    }
    #pragma unroll
    for (int i = 0; i < 4; i++) {
        int s = tid + i * 512;
        int row = s >> 4, seg = s & 15;
        cpa16(base + SM_WR2 + row * WSTR + seg * 16, wr2 + row * 128 + seg * 8);
    }
    if (tid < 256) {
        int t = tid;
        if (t < 32)       cpa16(base + SM_PAR + (PAR_AOBB + t * 4) * 4,         aob_bias + t * 4);
        else if (t < 64)  cpa16(base + SM_PAR + (PAR_OPB1 + (t - 32) * 4) * 4,  op_b1 + (t - 32) * 4);
        else if (t < 96)  cpa16(base + SM_PAR + (PAR_RB1 + (t - 64) * 4) * 4,   r_b1 + (t - 64) * 4);
        else if (t < 128) cpa16(base + SM_PAR + (PAR_RB2 + (t - 96) * 4) * 4,   r_b2 + (t - 96) * 4);
        else if (t < 160) cpa16(base + SM_PAR + (PAR_LN1G + (t - 128) * 4) * 4, ln1_g + (t - 128) * 4);
        else if (t < 192) cpa16(base + SM_PAR + (PAR_LN1B + (t - 160) * 4) * 4, ln1_b + (t - 160) * 4);
        else if (t < 224) cpa16(base + SM_PAR + (PAR_RLNG + (t - 192) * 4) * 4, rln_g + (t - 192) * 4);
        else              cpa16(base + SM_PAR + (PAR_RLNB + (t - 224) * 4) * 4, rln_b + (t - 224) * 4);

        if (t < 32)       cpa16(base + SM_PAR + (PAR_LN2G + t * 4) * 4,          ln2_g + t * 4);
        else if (t < 64)  cpa16(base + SM_PAR + (PAR_LN2B + (t - 32) * 4) * 4,   ln2_b + (t - 32) * 4);
        else if (t < 160) cpa16(base + SM_PAR + (PAR_W3 + (t - 64) * 4) * 4,     w3 + (t - 64) * 4);
        else if (t < 224) cpa16(base + SM_PAR + (PAR_LNFG + (t - 160) * 4) * 4,  lnf_g + (t - 160) * 4);

        if (t < 64)       cpa16(base + SM_PAR + (PAR_LNFB + t * 4) * 4,          lnf_b + t * 4);
        else if (t < 67)  cpa4(base + SM_PAR + (PAR_LNFG + 256 + (t - 64)) * 4,  lnf_g + 256 + (t - 64));
        else if (t < 70)  cpa4(base + SM_PAR + (PAR_LNFB + 256 + (t - 67)) * 4,  lnf_b + 256 + (t - 67));
        else if (t < 73)  cpa4(base + SM_PAR + (PAR_B3 + (t - 70)) * 4,          b3 + (t - 70));
    }
    asm volatile("cp.async.commit_group;");

    // ---- combine flash K-split partials (8 slices) ----
    {
        int r = tid >> 4, q = tid & 15;
        int grow = bm * 32 + r;
        int h = q >> 2;
        float L = 0.f;
        #pragma unroll
        for (int sp = 0; sp < KSPLIT; sp++)
            L += lpart[sp * NHEAD * NATOMS + h * NATOMS + grow];
        float inv = 1.f / L;
        const float* o0p = opart + grow * 128 + q * 8;
        uint32_t pk[4];
        #pragma unroll
        for (int i = 0; i < 2; i++) {
            float4 a = *(const float4*)&o0p[4 * i];
            #pragma unroll
            for (int sp = 1; sp < KSPLIT; sp++) {
                float4 b = *(const float4*)&o0p[sp * NATOMS * HDIM + 4 * i];
                a.x += b.x; a.y += b.y; a.z += b.z; a.w += b.w;
            }
            pk[2 * i]     = packbf(a.x * inv, a.y * inv);
            pk[2 * i + 1] = packbf(a.z * inv, a.w * inv);
        }
        *(uint4*)(dsm + SM_ACT + r * ASTR + q * 16) = *(uint4*)&pk[0];
    }

    asm volatile("cp.async.wait_group 0;");
    __syncthreads();

    const int i7 = lane & 7, sel = lane >> 3;
    const int arow = ((sel & 1) ? 8 : 0) + i7;
    const int acol = (sel >> 1) ? 16 : 0;
    const int vrow = ((sel & 1) ? 8 : 0) + i7;
    const int vcol = (sel >= 2) ? 16 : 0;
    const int htid = tid & 255;
    const int row = htid >> 4, q = htid & 15;
    const int grow = bm * 32 + hb * 16 + row;
    const int sr0 = lane >> 2;
    const int c2 = (lane & 3) * 2;
    const int barid = hb + 1;

    float acc[2][4];
    uint32_t hkeep[4];

    auto do_gemm = [&](int wOff, int ksteps) {
        #pragma unroll
        for (int j = 0; j < 2; j++)
            #pragma unroll
            for (int c = 0; c < 4; c++) acc[j][c] = 0.f;
        for (int ks = 0; ks < ksteps; ks++) {
            #pragma unroll
            for (int kh = 0; kh < 2; kh++) {
                uint32_t qa[4];
                ldsm4(qa[0], qa[1], qa[2], qa[3], aAct + arow * ASTR + ks * 64 + kh * 32 + acol);
                uint32_t r0, r1, r2, r3;
                ldsm4t(r0, r1, r2, r3,
                       base + wOff + (ks * 32 + kh * 16 + vrow) * WSTR + wc * 32 + vcol);
                mma16816(acc[0], qa, r0, r1);
                mma16816(acc[1], qa, r2, r3);
            }
        }
    };

    auto stage = [&](const float* bias) {
        #pragma unroll
        for (int t = 0; t < 2; t++) {
            int col = wc * 16 + t * 8 + c2;
            float a0 = bias[col], a1 = bias[col + 1];
            sSh[sr0 * 136 + col] = acc[t][0] + a0;       sSh[sr0 * 136 + col + 1] = acc[t][1] + a1;
            sSh[(sr0 + 8) * 136 + col] = acc[t][2] + a0; sSh[(sr0 + 8) * 136 + col + 1] = acc[t][3] + a1;
        }
    };

    // ============ stage 0: xa = aob @ wao + b ; comb-LN(259) ============
    do_gemm(SM_WAO, 4);
    stage(par + PAR_AOBB);
    barh(barid);
    {
        int bi = bidx[grow];
        float xv[8], cv[8];
        #pragma unroll
        for (int i = 0; i < 2; i++) {
            float4 f = *(const float4*)&sSh[row * 136 + q * 8 + i * 4];
            xv[4 * i] = f.x; xv[4 * i + 1] = f.y; xv[4 * i + 2] = f.z; xv[4 * i + 3] = f.w;
            float4 c = *(const float4*)&cf[bi * 128 + q * 8 + i * 4];
            cv[4 * i] = c.x; cv[4 * i + 1] = c.y; cv[4 * i + 2] = c.z; cv[4 * i + 3] = c.w;
        }
        float c0 = 0.f, c1 = 0.f, c2v = 0.f;
        float s = 0.f;
        #pragma unroll
        for (int i = 0; i < 8; i++) s += xv[i] + cv[i];
        if (q == 0) {
            c0 = coordp[grow * 3 + 0]; c1 = coordp[grow * 3 + 1]; c2v = coordp[grow * 3 + 2];
            s += c0 + c1 + c2v;
        }
        s += __shfl_xor_sync(0xffffffffu, s, 1);
        s += __shfl_xor_sync(0xffffffffu, s, 2);
        s += __shfl_xor_sync(0xffffffffu, s, 4);
        s += __shfl_xor_sync(0xffffffffu, s, 8);
        float mean = s * (1.f / 259.f);
        float sq = 0.f;
        #pragma unroll
        for (int i = 0; i < 8; i++) {
            float d0 = xv[i] - mean, d1 = cv[i] - mean;
            sq += d0 * d0 + d1 * d1;
        }
        if (q == 0) {
            float d0 = c0 - mean, d1 = c1 - mean, d2 = c2v - mean;
            sq += d0 * d0 + d1 * d1 + d2 * d2;
        }
        sq += __shfl_xor_sync(0xffffffffu, sq, 1);
        sq += __shfl_xor_sync(0xffffffffu, sq, 2);
        sq += __shfl_xor_sync(0xffffffffu, sq, 4);
        sq += __shfl_xor_sync(0xffffffffu, sq, 8);
        float inv = rsqrtf(sq * (1.f / 259.f) + 1e-5f);

        uint32_t pk[4];
        #pragma unroll
        for (int i = 0; i < 4; i++) {
            int ca = q * 8 + 2 * i;
            pk[i] = packbf((xv[2 * i] - mean) * inv * par[PAR_LNFG + ca] + par[PAR_LNFB + ca],
                           (xv[2 * i + 1] - mean) * inv * par[PAR_LNFG + ca + 1] + par[PAR_LNFB + ca + 1]);
        }
        *(uint4*)(dsm + SM_ACT + (hb * 16 + row) * ASTR + q * 16) = *(uint4*)&pk[0];
        #pragma unroll
        for (int i = 0; i < 4; i++) {
            int ca = 128 + q * 8 + 2 * i;
            pk[i] = packbf((cv[2 * i] - mean) * inv * par[PAR_LNFG + ca] + par[PAR_LNFB + ca],
                           (cv[2 * i + 1] - mean) * inv * par[PAR_LNFG + ca + 1] + par[PAR_LNFB + ca + 1]);
        }
        *(uint4*)(dsm + SM_ACT + (hb * 16 + row) * ASTR + 256 + q * 16) = *(uint4*)&pk[0];
        if (q == 0) {
            uint32_t tp0 = packbf((c0 - mean) * inv * par[PAR_LNFG + 256] + par[PAR_LNFB + 256],
                                  (c1 - mean) * inv * par[PAR_LNFG + 257] + par[PAR_LNFB + 257]);
            uint32_t tp1 = packbf((c2v - mean) * inv * par[PAR_LNFG + 258] + par[PAR_LNFB + 258], 0.f);
            *(uint2*)(dsm + SM_ACT + (hb * 16 + row) * ASTR + 512) = make_uint2(tp0, tp1);
        } else if (q >= 2) {
            *(uint32_t*)(dsm + SM_ACT + (hb * 16 + row) * ASTR + 512 + q * 4) = 0u;
        }
    }
    barh(barid);

    // ============ stage 1: h0 = comb @ wop1 ; LN + SiLU ============
    do_gemm(SM_WOP1, 9);
    stage(par + PAR_OPB1);
    barh(barid);
    {
        float v[8];
        #pragma unroll
        for (int i = 0; i < 2; i++) {
            float4 f = *(const float4*)&sSh[row * 136 + q * 8 + i * 4];
            v[4 * i] = f.x; v[4 * i + 1] = f.y; v[4 * i + 2] = f.z; v[4 * i + 3] = f.w;
        }
        float s = 0.f;
        #pragma unroll
        for (int i = 0; i < 8; i++) s += v[i];
        s += __shfl_xor_sync(0xffffffffu, s, 1);
        s += __shfl_xor_sync(0xffffffffu, s, 2);
        s += __shfl_xor_sync(0xffffffffu, s, 4);
        s += __shfl_xor_sync(0xffffffffu, s, 8);
        float mean = s * (1.f / 128.f);
        float sq = 0.f;
        #pragma unroll
        for (int i = 0; i < 8; i++) { float d = v[i] - mean; sq += d * d; }
        sq += __shfl_xor_sync(0xffffffffu, sq, 1);
        sq += __shfl_xor_sync(0xffffffffu, sq, 2);
        sq += __shfl_xor_sync(0xffffffffu, sq, 4);
        sq += __shfl_xor_sync(0xffffffffu, sq, 8);
        float inv = rsqrtf(sq * (1.f / 128.f) + 1e-5f);
        #pragma unroll
        for (int i = 0; i < 4; i++) {
            int ca = q * 8 + 2 * i;
            float y0 = silu_f((v[2 * i] - mean) * inv * par[PAR_LN1G + ca] + par[PAR_LN1B + ca]);
            float y1 = silu_f((v[2 * i + 1] - mean) * inv * par[PAR_LN1G + ca + 1] + par[PAR_LN1B + ca + 1]);
            hkeep[i] = packbf(y0, y1);
        }
        *(uint4*)(dsm + SM_ACT + (hb * 16 + row) * ASTR + q * 16) = *(uint4*)&hkeep[0];
    }
    barh(barid);

    // ============ stage 2: t = h1 @ wr1 ; LN + SiLU ============
    do_gemm(SM_WR1, 4);
    stage(par + PAR_RB1);
    barh(barid);
    {
        float v[8];
        #pragma unroll
        for (int i = 0; i < 2; i++) {
            float4 f = *(const float4*)&sSh[row * 136 + q * 8 + i * 4];
            v[4 * i] = f.x; v[4 * i + 1] = f.y; v[4 * i + 2] = f.z; v[4 * i + 3] = f.w;
        }
        float s = 0.f;
        #pragma unroll
        for (int i = 0; i < 8; i++) s += v[i];
        s += __shfl_xor_sync(0xffffffffu, s, 1);
        s += __shfl_xor_sync(0xffffffffu, s, 2);
        s += __shfl_xor_sync(0xffffffffu, s, 4);
        s += __shfl_xor_sync(0xffffffffu, s, 8);
        float mean = s * (1.f / 128.f);
        float sq = 0.f;
        #pragma unroll
        for (int i = 0; i < 8; i++) { float d = v[i] - mean; sq += d * d; }
        sq += __shfl_xor_sync(0xffffffffu, sq, 1);
        sq += __shfl_xor_sync(0xffffffffu, sq, 2);
        sq += __shfl_xor_sync(0xffffffffu, sq, 4);
        sq += __shfl_xor_sync(0xffffffffu, sq, 8);
        float inv = rsqrtf(sq * (1.f / 128.f) + 1e-5f);
        uint32_t pk[4];
        #pragma unroll
        for (int i = 0; i < 4; i++) {
            int ca = q * 8 + 2 * i;
            float y0 = silu_f((v[2 * i] - mean) * inv * par[PAR_RLNG + ca] + par[PAR_RLNB + ca]);
            float y1 = silu_f((v[2 * i + 1] - mean) * inv * par[PAR_RLNG + ca + 1] + par[PAR_RLNB + ca + 1]);
            pk[i] = packbf(y0, y1);
        }
        *(uint4*)(dsm + SM_ACT + (hb * 16 + row) * ASTR + q * 16) = *(uint4*)&pk[0];
    }
    barh(barid);

    // ============ stage 3: hfin = t2 @ wr2 + b + h1 ; LN ; proj/tanh/clamp ============
    do_gemm(SM_WR2, 4);
    stage(par + PAR_RB2);
    barh(barid);
    {
        float v[8];
        #pragma unroll
        for (int i = 0; i < 2; i++) {
            float4 f = *(const float4*)&sSh[row * 136 + q * 8 + i * 4];
            v[4 * i] = f.x; v[4 * i + 1] = f.y; v[4 * i + 2] = f.z; v[4 * i + 3] = f.w;
        }
        #pragma unroll
        for (int i = 0; i < 4; i++) {
            __nv_bfloat162 hh = *(__nv_bfloat162*)&hkeep[i];
            v[2 * i]     += __bfloat162float(hh.x);
            v[2 * i + 1] += __bfloat162float(hh.y);
        }
        float s = 0.f;
        #pragma unroll
        for (int i = 0; i < 8; i++) s += v[i];
        s += __shfl_xor_sync(0xffffffffu, s, 1);
        s += __shfl_xor_sync(0xffffffffu, s, 2);
        s += __shfl_xor_sync(0xffffffffu, s, 4);
        s += __shfl_xor_sync(0xffffffffu, s, 8);
        float mean = s * (1.f / 128.f);
        float sq = 0.f;
        #pragma unroll
        for (int i = 0; i < 8; i++) { float d = v[i] - mean; sq += d * d; }
        sq += __shfl_xor_sync(0xffffffffu, sq, 1);
        sq += __shfl_xor_sync(0xffffffffu, sq, 2);
        sq += __shfl_xor_sync(0xffffffffu, sq, 4);
        sq += __shfl_xor_sync(0xffffffffu, sq, 8);
        float inv = rsqrtf(sq * (1.f / 128.f) + 1e-5f);

        float p0 = 0.f, p1 = 0.f, p2 = 0.f;
        #pragma unroll
        for (int i = 0; i < 8; i++) {
            int ca = q * 8 + i;
            float y = (v[i] - mean) * inv * par[PAR_LN2G + ca] + par[PAR_LN2B + ca];
            p0 += y * par[PAR_W3 + ca * 3 + 0];
            p1 += y * par[PAR_W3 + ca * 3 + 1];
            p2 += y * par[PAR_W3 + ca * 3 + 2];
        }
        #pragma unroll
        for (int off = 8; off > 0; off >>= 1) {
            p0 += __shfl_xor_sync(0xffffffffu, p0, off);
            p1 += __shfl_xor_sync(0xffffffffu, p1, off);
            p2 += __shfl_xor_sync(0xffffffffu, p2, off);
        }
        if (q == 0) {
            int bi = bidx[grow];
            float dots[3] = {p0 + par[PAR_B3 + 0], p1 + par[PAR_B3 + 1], p2 + par[PAR_B3 + 2]};
            #pragma unroll
            for (int j = 0; j < 3; j++) {
                float val = coordp[grow * 3 + j] + 0.01f * tanhf(dots[j]);
                fout[grow * 3 + j] = fminf(fmaxf(val, bmin[bi * 3 + j]), bmax[bi * 3 + j]);
            }
        }
    }
}

// ======== flash: fp8 QK, 128 q-rows/CTA (2 m-tiles/warp), KSPLIT=8 ========
#define QSTRIDE 48
#define VSTRIDE 80
#define QBUF    6144     // 128 rows * 48
#define KB8     6144
#define VB16    10240
#define KVPAIR  (KB8 + VB16)
#define NITER   (32 / KSPLIT)

__device__ __forceinline__ void kv_load128(const uint8_t* __restrict__ Kf,
                                           const __nv_bfloat16* __restrict__ Vh,
                                           int h, int kb, uint32_t sbase, int tid) {
    #pragma unroll
    for (int i = 0; i < 2; i++) {
        cpa16(sbase + tid * QSTRIDE + i * 16,
              Kf + (((h << 12) + (kb << 7) + tid) << 5) + i * 16);
    }
    #pragma unroll
    for (int i = 0; i < 4; i++) {
        cpa16(sbase + KB8 + tid * VSTRIDE + i * 16,
              Vh + (((h << 12) + (kb << 7) + tid) << 5) + i * 8);
    }
    asm volatile("cp.async.commit_group;");
}

__global__ void __launch_bounds__(128) flashb_k(const uint8_t* __restrict__ Qf,
                                                const uint8_t* __restrict__ Kf,
                                                const __nv_bfloat16* __restrict__ Vh,
                                                float* __restrict__ opart,
                                                float* __restrict__ lpart) {
    __shared__ __align__(16) char smem[QBUF + 2 * KVPAIR];
    const int tid = threadIdx.x, lane = tid & 31, warp = tid >> 5;
    const int h = blockIdx.y, qb = blockIdx.x, sp = blockIdx.z;
    const int kb0 = sp * NITER;

    uint32_t Qsa = (uint32_t)__cvta_generic_to_shared(smem);
    uint32_t kva0 = Qsa + QBUF;
    uint32_t kva1 = Qsa + QBUF + KVPAIR;

    // load 128 Q rows (fp8, 32B each)
    #pragma unroll
    for (int i = 0; i < 2; i++) {
        int s = tid + i * 128;
        int row = s >> 1, seg = s & 1;
        uint4 v = *(const uint4*)(Qf + (((h << 12) + (qb << 7) + row) << 5) + seg * 16);
        *(uint4*)(smem + row * QSTRIDE + seg * 16) = v;
    }
    kv_load128(Kf, Vh, h, kb0 + 0, kva0, tid);
    kv_load128(Kf, Vh, h, kb0 + 1, kva1, tid);
    __syncthreads();

    // Q fragments: 2 m16-tiles per warp, k32 fp8
    uint32_t qa[8];
    {
        int i = lane & 7, sl = lane >> 3;
        #pragma unroll
        for (int mt = 0; mt < 2; mt++) {
            int row = warp * 32 + mt * 16 + ((sl & 1) ? 8 : 0) + i;
            uint32_t a = Qsa + row * QSTRIDE + ((sl >> 1) ? 16 : 0);
            ldsm4(qa[mt * 4 + 0], qa[mt * 4 + 1], qa[mt * 4 + 2], qa[mt * 4 + 3], a);
        }
    }

    float l00 = 0.f, l01 = 0.f, l10 = 0.f, l11 = 0.f;
    float o0[4][4], o1[4][4];
    #pragma unroll
    for (int j = 0; j < 4; j++)
        #pragma unroll
        for (int c = 0; c < 4; c++) { o0[j][c] = 0.f; o1[j][c] = 0.f; }

    const int i7 = lane & 7, sel = lane >> 3;
    const uint32_t krow = ((sel >= 2) ? 8 : 0) + i7;
    const uint32_t kcol = (sel & 1) ? 16 : 0;
    const uint32_t vrow = ((sel & 1) ? 8 : 0) + i7;
    const uint32_t vcol = (sel >= 2) ? 16 : 0;

    for (int kb = 0; kb < NITER; kb++) {
        if (kb < NITER - 1) asm volatile("cp.async.wait_group 1;");
        else                asm volatile("cp.async.wait_group 0;");
        __syncthreads();
        uint32_t Kbase = (kb & 1) ? kva1 : kva0;
        uint32_t Vbase = Kbase + KB8;

        #pragma unroll
        for (int ks = 0; ks < 8; ks++) {
            uint32_t a = Kbase + (ks * 16 + krow) * QSTRIDE + kcol;
            uint32_t b0, b1, b2, b3;
            ldsm4(b0, b1, b2, b3, a);

            float s00[4] = {0.f, 0.f, 0.f, 0.f}, s01[4] = {0.f, 0.f, 0.f, 0.f};
            float s10[4] = {0.f, 0.f, 0.f, 0.f}, s11[4] = {0.f, 0.f, 0.f, 0.f};
            mma16832(s00, qa,     b0, b1);
            mma16832(s01, qa,     b2, b3);
            mma16832(s10, qa + 4, b0, b1);
            mma16832(s11, qa + 4, b2, b3);

            uint32_t e00 = schexp(s00[0]), e01 = schexp(s00[1]);
            uint32_t e02 = schexp(s00[2]), e03 = schexp(s00[3]);
            uint32_t f00 = schexp(s01[0]), f01 = schexp(s01[1]);
            uint32_t f02 = schexp(s01[2]), f03 = schexp(s01[3]);
            uint32_t e10 = schexp(s10[0]), e11 = schexp(s10[1]);
            uint32_t e12 = schexp(s10[2]), e13 = schexp(s10[3]);
            uint32_t f10 = schexp(s11[0]), f11 = schexp(s11[1]);
            uint32_t f12 = schexp(s11[2]), f13 = schexp(s11[3]);

            l00 += (__int_as_float(e00) + __int_as_float(e01))
                 + (__int_as_float(f00) + __int_as_float(f01));
            l01 += (__int_as_float(e02) + __int_as_float(e03))
                 + (__int_as_float(f02) + __int_as_float(f03));
            l10 += (__int_as_float(e10) + __int_as_float(e11))
                 + (__int_as_float(f10) + __int_as_float(f11));
            l11 += (__int_as_float(e12) + __int_as_float(e13))
                 + (__int_as_float(f12) + __int_as_float(f13));

            uint32_t pa0[4], pa1[4];
            pa0[0] = prmt16(e00, e01); pa0[1] = prmt16(e02, e03);
            pa0[2] = prmt16(f00, f01); pa0[3] = prmt16(f02, f03);
            pa1[0] = prmt16(e10, e11); pa1[1] = prmt16(e12, e13);
            pa1[2] = prmt16(f10, f11); pa1[3] = prmt16(f12, f13);

            uint32_t av = Vbase + (ks * 16 + vrow) * VSTRIDE + vcol;
            uint32_t v0, v1, v2, v3, w0, w1, w2, w3;
            ldsm4t(v0, v1, v2, v3, av);
            ldsm4t(w0, w1, w2, w3, av + 32);
            mma16816(o0[0], pa0, v0, v1);
            mma16816(o0[1], pa0, v2, v3);
            mma16816(o0[2], pa0, w0, w1);
            mma16816(o0[3], pa0, w2, w3);
            mma16816(o1[0], pa1, v0, v1);
            mma16816(o1[1], pa1, v2, v3);
            mma16816(o1[2], pa1, w0, w1);
            mma16816(o1[3], pa1, w2, w3);
        }

        __syncthreads();
        if (kb < NITER - 2) kv_load128(Kf, Vh, h, kb0 + kb + 2, (kb & 1) ? kva1 : kva0, tid);
    }

    l00 += __shfl_xor_sync(0xffffffffu, l00, 1);
    l00 += __shfl_xor_sync(0xffffffffu, l00, 2);
    l01 += __shfl_xor_sync(0xffffffffu, l01, 1);
    l01 += __shfl_xor_sync(0xffffffffu, l01, 2);
    l10 += __shfl_xor_sync(0xffffffffu, l10, 1);
    l10 += __shfl_xor_sync(0xffffffffu, l10, 2);
    l11 += __shfl_xor_sync(0xffffffffu, l11, 1);
    l11 += __shfl_xor_sync(0xffffffffu, l11, 2);

    int g = lane >> 2, l2 = (lane & 3) * 2;
    int row0 = (qb << 7) + warp * 32 + g;
    float* op = opart + sp * NATOMS * HDIM;
    #pragma unroll
    for (int j = 0; j < 4; j++) {
        int col = (h << 5) + j * 8 + l2;
        *(float2*)&op[row0 * HDIM + col]        = make_float2(o0[j][0], o0[j][1]);
        *(float2*)&op[(row0 + 8) * HDIM + col]  = make_float2(o0[j][2], o0[j][3]);
        *(float2*)&op[(row0 + 16) * HDIM + col] = make_float2(o1[j][0], o1[j][1]);
        *(float2*)&op[(row0 + 24) * HDIM + col] = make_float2(o1[j][2], o1[j][3]);
    }
    if ((lane & 3) == 0) {
        float* lp = lpart + sp * NHEAD * NATOMS + h * NATOMS;
        lp[row0]      = l00;
        lp[row0 + 8]  = l01;
        lp[row0 + 16] = l10;
        lp[row0 + 24] = l11;
    }
}

// ---------------- host ----------------
extern "C" void kernel_launch(void* const* d_in, const int* in_sizes, int n_in,
                              void* d_out, int out_size) {
    const int*   num_atoms  = (const int*)d_in[0];
    const int*   elems      = (const int*)d_in[1];
    const float* cell       = (const float*)d_in[2];
    const float* coord      = (const float*)d_in[3];
    const float* emb        = (const float*)d_in[4];
    const float* ln_in_g    = (const float*)d_in[5];
    const float* ln_in_b    = (const float*)d_in[6];
    const float* attn_in_w  = (const float*)d_in[7];
    const float* attn_in_b  = (const float*)d_in[8];
    const float* attn_out_w = (const float*)d_in[9];
    const float* attn_out_b = (const float*)d_in[10];
    const float* ce_w1      = (const float*)d_in[11];
    const float* ce_b1      = (const float*)d_in[12];
    const float* ce_w2      = (const float*)d_in[13];
    const float* ce_b2      = (const float*)d_in[14];
    const float* ln_feat_g  = (const float*)d_in[15];
    const float* ln_feat_b  = (const float*)d_in[16];
    const float* op_w1      = (const float*)d_in[17];
    const float* op_b1      = (const float*)d_in[18];
    const float* op_ln1_g   = (const float*)d_in[19];
    const float* op_ln1_b   = (const float*)d_in[20];
    const float* res_w1     = (const float*)d_in[21];
    const float* res_b1     = (const float*)d_in[22];
    const float* res_ln_g   = (const float*)d_in[23];
    const float* res_ln_b   = (const float*)d_in[24];
    const float* res_w2     = (const float*)d_in[25];
    const float* res_b2     = (const float*)d_in[26];
    const float* op_ln2_g   = (const float*)d_in[27];
    const float* op_ln2_b   = (const float*)d_in[28];
    const float* op_w3      = (const float*)d_in[29];
    const float* op_b3      = (const float*)d_in[30];
    float* out = (float*)d_out;

    float* S = nullptr;
    cudaGetSymbolAddress((void**)&S, g_scratch);
    int* bidx = nullptr;
    cudaGetSymbolAddress((void**)&bidx, g_bidx);

    __nv_bfloat16* P = (__nv_bfloat16*)S;
    __nv_bfloat16* xb    = P; P += NATOMS * HDIM;
    __nv_bfloat16* Vh    = P; P += NATOMS * HDIM;
    __nv_bfloat16* wqkv  = P; P += 128 * 384;
    __nv_bfloat16* wao   = P; P += 128 * 128;
    __nv_bfloat16* wop1  = P; P += FPAD * 128;
    __nv_bfloat16* wr1   = P; P += 128 * 128;
    __nv_bfloat16* wr2   = P; P += 128 * 128;
    uint8_t* U = (uint8_t*)P;
    uint8_t* Qf = U; U += NATOMS * HDIM;
    uint8_t* Kf = U; U += NATOMS * HDIM;
    U = (uint8_t*)(((uintptr_t)U + 15) & ~(uintptr_t)15);
    float* F = (float*)U;
    float* opart = F; F += KSPLIT * NATOMS * HDIM;
    float* lpart = F; F += KSPLIT * NHEAD * NATOMS;
    float* cf    = F; F += BATCH * HDIM;
    float* bmin  = F; F += BATCH * 3;
    float* bmax  = F; F += BATCH * 3;

    static bool attr_set = false;
    if (!attr_set) {
        cudaFuncSetAttribute(tail_k, cudaFuncAttributeMaxDynamicSharedMemorySize, SMEM_TAIL);
        attr_set = true;
    }

    setup_k<<<1049, 256>>>(elems, emb, ln_in_g, ln_in_b, xb,
                           attn_in_w, attn_out_w, op_w1, res_w1, res_w2,
                           wqkv, wao, wop1, wr1, wr2,
                           cell, ce_w1, ce_b1, ce_w2, ce_b2, cf,
                           num_atoms, bmin, bmax);

    qkv_k<<<dim3(3, 128), 128>>>(xb, wqkv, attn_in_b, Qf, Kf, Vh);

    flashb_k<<<dim3(32, NHEAD, KSPLIT), 128>>>(Qf, Kf, Vh, opart, lpart);

    tail_k<<<128, 512, SMEM_TAIL>>>(opart, lpart,
        wao, attn_out_b, ln_feat_g, ln_feat_b, cf, coord, bidx,
        wop1, op_b1, op_ln1_g, op_ln1_b,
        wr1, res_b1, res_ln_g, res_ln_b,
        wr2, res_b2, op_ln2_g, op_ln2_b,
        op_w3, op_b3, bmin, bmax, out);
}

// round 14
// speedup vs baseline: 8.1886x; 1.0060x over previous
#include <cuda_runtime.h>
#include <cuda_bf16.h>
#include <math.h>
#include <stdint.h>

#define NATOMS 4096
#define HDIM   128
#define BATCH  128
#define NHEAD  4
#define DHEAD  32
#define H3     384
#define FPAD   288
#define KSPLIT 8

// -------- scratch (no allocations allowed) --------
__device__ float g_scratch[8300000];
__device__ int   g_bidx[NATOMS];

// ---------------- helpers ----------------
__device__ __forceinline__ float silu_f(float x) {
    return x / (1.f + __expf(-x));
}
__device__ __forceinline__ void ldsm4(uint32_t& r0, uint32_t& r1, uint32_t& r2, uint32_t& r3, uint32_t addr) {
    asm volatile("ldmatrix.sync.aligned.m8n8.x4.shared.b16 {%0,%1,%2,%3}, [%4];"
                 : "=r"(r0), "=r"(r1), "=r"(r2), "=r"(r3) : "r"(addr));
}
__device__ __forceinline__ void ldsm4t(uint32_t& r0, uint32_t& r1, uint32_t& r2, uint32_t& r3, uint32_t addr) {
    asm volatile("ldmatrix.sync.aligned.m8n8.x4.trans.shared.b16 {%0,%1,%2,%3}, [%4];"
                 : "=r"(r0), "=r"(r1), "=r"(r2), "=r"(r3) : "r"(addr));
}
__device__ __forceinline__ void mma16816(float* d, const uint32_t* a, uint32_t b0, uint32_t b1) {
    asm volatile("mma.sync.aligned.m16n8k16.row.col.f32.bf16.bf16.f32 "
                 "{%0,%1,%2,%3}, {%4,%5,%6,%7}, {%8,%9}, {%0,%1,%2,%3};"
                 : "+f"(d[0]), "+f"(d[1]), "+f"(d[2]), "+f"(d[3])
                 : "r"(a[0]), "r"(a[1]), "r"(a[2]), "r"(a[3]), "r"(b0), "r"(b1));
}
__device__ __forceinline__ void mma16832(float* d, const uint32_t* a, uint32_t b0, uint32_t b1) {
    asm volatile("mma.sync.aligned.m16n8k32.row.col.f32.e4m3.e4m3.f32 "
                 "{%0,%1,%2,%3}, {%4,%5,%6,%7}, {%8,%9}, {%0,%1,%2,%3};"
                 : "+f"(d[0]), "+f"(d[1]), "+f"(d[2]), "+f"(d[3])
                 : "r"(a[0]), "r"(a[1]), "r"(a[2]), "r"(a[3]), "r"(b0), "r"(b1));
}
__device__ __forceinline__ uint32_t packbf(float lo, float hi) {
    uint32_t r;
    asm volatile("cvt.rn.bf16x2.f32 %0, %1, %2;" : "=r"(r) : "f"(hi), "f"(lo));
    return r;
}
__device__ __forceinline__ uint16_t packe4(float lo, float hi) {
    uint16_t r;
    asm volatile("cvt.rn.satfinite.e4m3x2.f32 %0, %1, %2;" : "=h"(r) : "f"(hi), "f"(lo));
    return r;
}
__device__ __forceinline__ void cpa16(uint32_t dst, const void* src) {
    asm volatile("cp.async.ca.shared.global [%0], [%1], 16;" :: "r"(dst), "l"(src));
}
__device__ __forceinline__ void cpa4(uint32_t dst, const void* src) {
    asm volatile("cp.async.ca.shared.global [%0], [%1], 4;" :: "r"(dst), "l"(src));
}
__device__ __forceinline__ void barh(int id) {
    asm volatile("bar.sync %0, 256;" :: "r"(id) : "memory");
}
__device__ __forceinline__ uint32_t schexp(float x) {
    int i;
    asm("cvt.rni.s32.f32 %0, %1;" : "=r"(i) : "f"(fmaf(x, 8388608.f, 1064876800.f)));
    return (uint32_t)i;
}
__device__ __forceinline__ uint32_t prmt16(uint32_t a, uint32_t b) {
    uint32_t r;
    asm("prmt.b32 %0,%1,%2,0x7632;" : "=r"(r) : "r"(a), "r"(b));
    return r;
}

// ================= fused setup kernel =================
__global__ void __launch_bounds__(256) setup_k(
    const int* __restrict__ elems, const float* __restrict__ emb,
    const float* __restrict__ ln_in_g, const float* __restrict__ ln_in_b,
    __nv_bfloat16* __restrict__ xo,
    const float* __restrict__ aiw, const float* __restrict__ aow,
    const float* __restrict__ opw1, const float* __restrict__ rw1,
    const float* __restrict__ rw2,
    __nv_bfloat16* __restrict__ wqkv, __nv_bfloat16* __restrict__ wao,
    __nv_bfloat16* __restrict__ wop1, __nv_bfloat16* __restrict__ wr1,
    __nv_bfloat16* __restrict__ wr2,
    const float* __restrict__ cell,
    const float* __restrict__ cw1, const float* __restrict__ cb1,
    const float* __restrict__ cw2, const float* __restrict__ cb2,
    float* __restrict__ cf,
    const int* __restrict__ num_atoms,
    float* __restrict__ bmin, float* __restrict__ bmax)
{
    const int b = blockIdx.x, tid = threadIdx.x;

    if (b < 512) {
        int warp = tid >> 5, lane = tid & 31;
        int r = b * 8 + warp;
        int e = elems[r];
        float4 v = *(const float4*)&emb[e * HDIM + lane * 4];
        float s = v.x + v.y + v.z + v.w;
        #pragma unroll
        for (int off = 16; off > 0; off >>= 1) s += __shfl_xor_sync(0xffffffffu, s, off);
        float mean = s * (1.f / 128.f);
        float dx = v.x - mean, dy = v.y - mean, dz = v.z - mean, dw = v.w - mean;
        float sq = dx * dx + dy * dy + dz * dz + dw * dw;
        #pragma unroll
        for (int off = 16; off > 0; off >>= 1) sq += __shfl_xor_sync(0xffffffffu, sq, off);
        float inv = rsqrtf(sq * (1.f / 128.f) + 1e-5f);
        float4 gg = *(const float4*)&ln_in_g[lane * 4];
        float4 bb = *(const float4*)&ln_in_b[lane * 4];
        uint32_t p0 = packbf(dx * inv * gg.x + bb.x, dy * inv * gg.y + bb.y);
        uint32_t p1 = packbf(dz * inv * gg.z + bb.z, dw * inv * gg.w + bb.w);
        *(uint2*)(xo + r * HDIM + lane * 4) = make_uint2(p0, p1);
        return;
    }

    if (b < 1040) {
        int i = (b - 512) * 256 + tid;
        if (i < 49152) wqkv[i] = __float2bfloat16(aiw[i]);
        else if (i < 65536) { int j = i - 49152; wao[j] = __float2bfloat16(aow[j]); }
        else if (i < 102400) {
            int j = i - 65536; int r = j >> 7, c = j & 127;
            wop1[j] = __float2bfloat16(r < 259 ? opw1[r * 128 + c] : 0.f);
        }
        else if (i < 118784) { int j = i - 102400; wr1[j] = __float2bfloat16(rw1[j]); }
        else { int j = i - 118784; wr2[j] = __float2bfloat16(rw2[j]); }
        return;
    }

    if (b < 1048) {
        __shared__ float t1s[16][128];
        int r0 = (b - 1040) * 16;
        #pragma unroll
        for (int i = 0; i < 8; i++) {
            int idx = tid + i * 256;
            int rr = idx >> 7, k = idx & 127;
            int r = r0 + rr;
            float u = cell[r * 3 + 0] * cw1[k] + cell[r * 3 + 1] * cw1[128 + k]
                    + cell[r * 3 + 2] * cw1[256 + k] + cb1[k];
            t1s[rr][k] = silu_f(u);
        }
        __syncthreads();
        int t = tid & 127, half = tid >> 7;
        float acc[8];
        #pragma unroll
        for (int j = 0; j < 8; j++) acc[j] = cb2[t];
        #pragma unroll 4
        for (int k = 0; k < 128; k++) {
            float w = cw2[k * 128 + t];
            #pragma unroll
            for (int j = 0; j < 8; j++) acc[j] += t1s[half * 8 + j][k] * w;
        }
        #pragma unroll
        for (int j = 0; j < 8; j++) cf[(r0 + half * 8 + j) * 128 + t] = acc[j];
        return;
    }

    __shared__ int starts[BATCH + 1];
    if (tid == 0) {
        int acc = 0;
        for (int i = 0; i < BATCH; i++) { starts[i] = acc; acc += num_atoms[i]; }
        starts[BATCH] = acc;
    }
    __syncthreads();
    for (int i = tid; i < NATOMS; i += 256) g_bidx[i] = BATCH - 1;
    __syncthreads();
    if (tid < BATCH) {
        int s = starts[tid], e = starts[tid + 1];
        if (s > NATOMS) s = NATOMS;
        if (e > NATOMS) e = NATOMS;
        for (int i = s; i < e; i++) g_bidx[i] = tid;
        #pragma unroll
        for (int i = 0; i < 3; i++) {
            float a = cell[(3 * tid + i) * 3 + 0];
            float c1 = cell[(3 * tid + i) * 3 + 1];
            float c = cell[(3 * tid + i) * 3 + 2];
            bmin[tid * 3 + i] = fminf(a, fminf(c1, c)) + 1e-6f;
            bmax[tid * 3 + i] = fmaxf(a, fmaxf(c1, c)) - 1e-6f;
        }
    }
}

// ================= QKV GEMM: Q,K -> e4m3 (scaled), V -> bf16 =================
__global__ void __launch_bounds__(128) qkv_k(
    const __nv_bfloat16* __restrict__ A, const __nv_bfloat16* __restrict__ W,
    const float* __restrict__ bias,
    uint8_t* __restrict__ Qf, uint8_t* __restrict__ Kf,
    __nv_bfloat16* __restrict__ Vh)
{
    __shared__ __align__(16) char sA[2 * 32 * 80];
    __shared__ __align__(16) char sW[2 * 32 * 272];
    const int tid = threadIdx.x, lane = tid & 31, warp = tid >> 5;
    const int wr = warp & 1, wc = warp >> 1;
    const int bm = blockIdx.y, nb = blockIdx.x;
    uint32_t aBase = (uint32_t)__cvta_generic_to_shared(sA);
    uint32_t wBase = (uint32_t)__cvta_generic_to_shared(sW);

    #pragma unroll
    for (int p = 0; p < 2; p++) {
        int row = tid >> 2, seg = tid & 3;
        cpa16(aBase + p * 2560 + row * 80 + seg * 16,
              A + (bm * 32 + row) * 128 + p * 32 + seg * 8);
        #pragma unroll
        for (int i = 0; i < 4; i++) {
            int s = tid + i * 128;
            int wrow = s >> 4, wseg = s & 15;
            cpa16(wBase + p * 8704 + wrow * 272 + wseg * 16,
                  W + (p * 32 + wrow) * H3 + nb * 128 + wseg * 8);
        }
        asm volatile("cp.async.commit_group;");
    }

    float acc[8][4];
    #pragma unroll
    for (int j = 0; j < 8; j++)
        #pragma unroll
        for (int c = 0; c < 4; c++) acc[j][c] = 0.f;

    const int i7 = lane & 7, sel = lane >> 3;
    const int arow = wr * 16 + ((sel & 1) ? 8 : 0) + i7;
    const int acol = (sel >> 1) ? 16 : 0;
    const int vrow = ((sel & 1) ? 8 : 0) + i7;
    const int vcol = (sel >= 2) ? 16 : 0;

    for (int ks = 0; ks < 4; ks++) {
        if (ks < 3) asm volatile("cp.async.wait_group 1;");
        else        asm volatile("cp.async.wait_group 0;");
        __syncthreads();
        uint32_t Ab = aBase + (ks & 1) * 2560;
        uint32_t Wb = wBase + (ks & 1) * 8704;
        #pragma unroll
        for (int kh = 0; kh < 2; kh++) {
            uint32_t qa[4];
            ldsm4(qa[0], qa[1], qa[2], qa[3], Ab + arow * 80 + acol + kh * 32);
            #pragma unroll
            for (int j = 0; j < 4; j++) {
                uint32_t r0, r1, r2, r3;
                ldsm4t(r0, r1, r2, r3, Wb + (kh * 16 + vrow) * 272 + wc * 128 + j * 32 + vcol);
                mma16816(acc[2 * j],     qa, r0, r1);
                mma16816(acc[2 * j + 1], qa, r2, r3);
            }
        }
        __syncthreads();
        if (ks + 2 < 4) {
            int p = ks + 2, buf = ks & 1;
            int row = tid >> 2, seg = tid & 3;
            cpa16(aBase + buf * 2560 + row * 80 + seg * 16,
                  A + (bm * 32 + row) * 128 + p * 32 + seg * 8);
            #pragma unroll
            for (int i = 0; i < 4; i++) {
                int s = tid + i * 128;
                int wrow = s >> 4, wseg = s & 15;
                cpa16(wBase + buf * 8704 + wrow * 272 + wseg * 16,
                      W + (p * 32 + wrow) * H3 + nb * 128 + wseg * 8);
            }
            asm volatile("cp.async.commit_group;");
        }
    }

    const int g = lane >> 2, c2 = (lane & 3) * 2;
    int r0 = bm * 32 + wr * 16 + g;
    const float SC = 0.50507248f;
    if (nb < 2) {
        uint8_t* outp = (nb == 0) ? Qf : Kf;
        #pragma unroll
        for (int t = 0; t < 8; t++) {
            int col = wc * 64 + t * 8 + c2;
            float b0v = bias[nb * 128 + col], b1v = bias[nb * 128 + col + 1];
            int h = col >> 5, d = col & 31;
            *(uint16_t*)(outp + (((h << 12) + r0) << 5) + d) =
                packe4((acc[t][0] + b0v) * SC, (acc[t][1] + b1v) * SC);
            *(uint16_t*)(outp + (((h << 12) + r0 + 8) << 5) + d) =
                packe4((acc[t][2] + b0v) * SC, (acc[t][3] + b1v) * SC);
        }
    } else {
        #pragma unroll
        for (int t = 0; t < 8; t++) {
            int col = wc * 64 + t * 8 + c2;
            float b0v = bias[256 + col], b1v = bias[256 + col + 1];
            int h = col >> 5, d = col & 31;
            *(uint32_t*)(Vh + (((h << 12) + r0) << 5) + d) =
                packbf(acc[t][0] + b0v, acc[t][1] + b1v);
            *(uint32_t*)(Vh + (((h << 12) + r0 + 8) << 5) + d) =
                packbf(acc[t][2] + b0v, acc[t][3] + b1v);
        }
    }
}

// ================= fused tail: 512 threads ==========
#define WSTR 272
#define ASTR 592
#define SM_WAO   0
#define SM_WOP1  (128 * WSTR)
#define SM_WR1   (SM_WOP1 + 288 * WSTR)
#define SM_WR2   (SM_WR1 + 128 * WSTR)
#define SM_ACT   (SM_WR2 + 128 * WSTR)
#define SM_STAGE (SM_ACT + 32 * ASTR)
#define SM_PAR   (SM_STAGE + 32 * 136 * 4)
#define PAR_AOBB 0
#define PAR_OPB1 128
#define PAR_RB1  256
#define PAR_RB2  384
#define PAR_LNFG 512
#define PAR_LNFB 772
#define PAR_LN1G 1032
#define PAR_LN1B 1160
#define PAR_RLNG 1288
#define PAR_RLNB 1416
#define PAR_LN2G 1544
#define PAR_LN2B 1672
#define PAR_W3   1800
#define PAR_B3   2184
#define SMEM_TAIL (SM_PAR + 2192 * 4)

__global__ void __launch_bounds__(512) tail_k(
    const __nv_bfloat16* __restrict__ opart, const float* __restrict__ lpart,
    const __nv_bfloat16* __restrict__ wao, const float* __restrict__ aob_bias,
    const float* __restrict__ lnf_g, const float* __restrict__ lnf_b,
    const float* __restrict__ cf, const float* __restrict__ coordp,
    const int* __restrict__ bidx,
    const __nv_bfloat16* __restrict__ wop1, const float* __restrict__ op_b1,
    const float* __restrict__ ln1_g, const float* __restrict__ ln1_b,
    const __nv_bfloat16* __restrict__ wr1, const float* __restrict__ r_b1,
    const float* __restrict__ rln_g, const float* __restrict__ rln_b,
    const __nv_bfloat16* __restrict__ wr2, const float* __restrict__ r_b2,
    const float* __restrict__ ln2_g, const float* __restrict__ ln2_b,
    const float* __restrict__ w3, const float* __restrict__ b3,
    const float* __restrict__ bmin, const float* __restrict__ bmax,
    float* __restrict__ fout)
{
    extern __shared__ __align__(16) char dsm[];
    const int tid = threadIdx.x, lane = tid & 31, warp = tid >> 5;
    const int hb = warp >> 3;
    const int wc = warp & 7;
    const int bm = blockIdx.x;
    uint32_t base = (uint32_t)__cvta_generic_to_shared(dsm);
    uint32_t aAct = base + SM_ACT + hb * 16 * ASTR;
    float* sSh = (float*)(dsm + SM_STAGE) + hb * 16 * 136;
    const float* par = (const float*)(dsm + SM_PAR);

    #pragma unroll
    for (int i = 0; i < 4; i++) {
        int s = tid + i * 512;
        int row = s >> 4, seg = s & 15;
        cpa16(base + SM_WAO + row * WSTR + seg * 16, wao + row * 128 + seg * 8);
    }
    #pragma unroll
    for (int i = 0; i < 9; i++) {
        int s = tid + i * 512;
        int row = s >> 4, seg = s & 15;
        cpa16(base + SM_WOP1 + row * WSTR + seg * 16, wop1 + row * 128 + seg * 8);
    }
    #pragma unroll
    for (int i = 0; i < 4; i++) {
        int s = tid + i * 512;
        int row = s >> 4, seg = s & 15;
        cpa16(base + SM_WR1 + row * WSTR + seg * 16, wr1 + row * 128 + seg * 8);
    }
    #pragma unroll
    for (int i = 0; i < 4; i++) {
        int s = tid + i * 512;
        int row = s >> 4, seg = s & 15;
        cpa16(base + SM_WR2 + row * WSTR + seg * 16, wr2 + row * 128 + seg * 8);
    }
    if (tid < 256) {
        int t = tid;
        if (t < 32)       cpa16(base + SM_PAR + (PAR_AOBB + t * 4) * 4,         aob_bias + t * 4);
        else if (t < 64)  cpa16(base + SM_PAR + (PAR_OPB1 + (t - 32) * 4) * 4,  op_b1 + (t - 32) * 4);
        else if (t < 96)  cpa16(base + SM_PAR + (PAR_RB1 + (t - 64) * 4) * 4,   r_b1 + (t - 64) * 4);
        else if (t < 128) cpa16(base + SM_PAR + (PAR_RB2 + (t - 96) * 4) * 4,   r_b2 + (t - 96) * 4);
        else if (t < 160) cpa16(base + SM_PAR + (PAR_LN1G + (t - 128) * 4) * 4, ln1_g + (t - 128) * 4);
        else if (t < 192) cpa16(base + SM_PAR + (PAR_LN1B + (t - 160) * 4) * 4, ln1_b + (t - 160) * 4);
        else if (t < 224) cpa16(base + SM_PAR + (PAR_RLNG + (t - 192) * 4) * 4, rln_g + (t - 192) * 4);
        else              cpa16(base + SM_PAR + (PAR_RLNB + (t - 224) * 4) * 4, rln_b + (t - 224) * 4);

        if (t < 32)       cpa16(base + SM_PAR + (PAR_LN2G + t * 4) * 4,          ln2_g + t * 4);
        else if (t < 64)  cpa16(base + SM_PAR + (PAR_LN2B + (t - 32) * 4) * 4,   ln2_b + (t - 32) * 4);
        else if (t < 160) cpa16(base + SM_PAR + (PAR_W3 + (t - 64) * 4) * 4,     w3 + (t - 64) * 4);
        else if (t < 224) cpa16(base + SM_PAR + (PAR_LNFG + (t - 160) * 4) * 4,  lnf_g + (t - 160) * 4);

        if (t < 64)       cpa16(base + SM_PAR + (PAR_LNFB + t * 4) * 4,          lnf_b + t * 4);
        else if (t < 67)  cpa4(base + SM_PAR + (PAR_LNFG + 256 + (t - 64)) * 4,  lnf_g + 256 + (t - 64));
        else if (t < 70)  cpa4(base + SM_PAR + (PAR_LNFB + 256 + (t - 67)) * 4,  lnf_b + 256 + (t - 67));
        else if (t < 73)  cpa4(base + SM_PAR + (PAR_B3 + (t - 70)) * 4,          b3 + (t - 70));
    }
    asm volatile("cp.async.commit_group;");

    // ---- combine flash K-split partials (8 slices, bf16) ----
    {
        int r = tid >> 4, q = tid & 15;
        int grow = bm * 32 + r;
        int h = q >> 2;
        float L = 0.f;
        #pragma unroll
        for (int sp = 0; sp < KSPLIT; sp++)
            L += lpart[sp * NHEAD * NATOMS + h * NATOMS + grow];
        float inv = 1.f / L;
        const __nv_bfloat16* o0p = opart + grow * 128 + q * 8;
        float av[8];
        #pragma unroll
        for (int i = 0; i < 8; i++) av[i] = 0.f;
        #pragma unroll
        for (int sp = 0; sp < KSPLIT; sp++) {
            uint4 u = *(const uint4*)(o0p + sp * NATOMS * HDIM);
            const uint32_t* uw = (const uint32_t*)&u;
            #pragma unroll
            for (int i = 0; i < 4; i++) {
                __nv_bfloat162 hh = *(__nv_bfloat162*)&uw[i];
                av[2 * i]     += __bfloat162float(hh.x);
                av[2 * i + 1] += __bfloat162float(hh.y);
            }
        }
        uint32_t pk[4];
        #pragma unroll
        for (int i = 0; i < 4; i++)
            pk[i] = packbf(av[2 * i] * inv, av[2 * i + 1] * inv);
        *(uint4*)(dsm + SM_ACT + r * ASTR + q * 16) = *(uint4*)&pk[0];
    }

    asm volatile("cp.async.wait_group 0;");
    __syncthreads();

    const int i7 = lane & 7, sel = lane >> 3;
    const int arow = ((sel & 1) ? 8 : 0) + i7;
    const int acol = (sel >> 1) ? 16 : 0;
    const int vrow = ((sel & 1) ? 8 : 0) + i7;
    const int vcol = (sel >= 2) ? 16 : 0;
    const int htid = tid & 255;
    const int row = htid >> 4, q = htid & 15;
    const int grow = bm * 32 + hb * 16 + row;
    const int sr0 = lane >> 2;
    const int c2 = (lane & 3) * 2;
    const int barid = hb + 1;

    float acc[2][4];
    uint32_t hkeep[4];

    auto do_gemm = [&](int wOff, int ksteps) {
        #pragma unroll
        for (int j = 0; j < 2; j++)
            #pragma unroll
            for (int c = 0; c < 4; c++) acc[j][c] = 0.f;
        for (int ks = 0; ks < ksteps; ks++) {
            #pragma unroll
            for (int kh = 0; kh < 2; kh++) {
                uint32_t qa[4];
                ldsm4(qa[0], qa[1], qa[2], qa[3], aAct + arow * ASTR + ks * 64 + kh * 32 + acol);
                uint32_t r0, r1, r2, r3;
                ldsm4t(r0, r1, r2, r3,
                       base + wOff + (ks * 32 + kh * 16 + vrow) * WSTR + wc * 32 + vcol);
                mma16816(acc[0], qa, r0, r1);
                mma16816(acc[1], qa, r2, r3);
            }
        }
    };

    auto stage = [&](const float* bias) {
        #pragma unroll
        for (int t = 0; t < 2; t++) {
            int col = wc * 16 + t * 8 + c2;
            float a0 = bias[col], a1 = bias[col + 1];
            sSh[sr0 * 136 + col] = acc[t][0] + a0;       sSh[sr0 * 136 + col + 1] = acc[t][1] + a1;
            sSh[(sr0 + 8) * 136 + col] = acc[t][2] + a0; sSh[(sr0 + 8) * 136 + col + 1] = acc[t][3] + a1;
        }
    };

    // ============ stage 0: xa = aob @ wao + b ; comb-LN(259) ============
    do_gemm(SM_WAO, 4);
    stage(par + PAR_AOBB);
    barh(barid);
    {
        int bi = bidx[grow];
        float xv[8], cv[8];
        #pragma unroll
        for (int i = 0; i < 2; i++) {
            float4 f = *(const float4*)&sSh[row * 136 + q * 8 + i * 4];
            xv[4 * i] = f.x; xv[4 * i + 1] = f.y; xv[4 * i + 2] = f.z; xv[4 * i + 3] = f.w;
            float4 c = *(const float4*)&cf[bi * 128 + q * 8 + i * 4];
            cv[4 * i] = c.x; cv[4 * i + 1] = c.y; cv[4 * i + 2] = c.z; cv[4 * i + 3] = c.w;
        }
        float c0 = 0.f, c1 = 0.f, c2v = 0.f;
        float s = 0.f;
        #pragma unroll
        for (int i = 0; i < 8; i++) s += xv[i] + cv[i];
        if (q == 0) {
            c0 = coordp[grow * 3 + 0]; c1 = coordp[grow * 3 + 1]; c2v = coordp[grow * 3 + 2];
            s += c0 + c1 + c2v;
        }
        s += __shfl_xor_sync(0xffffffffu, s, 1);
        s += __shfl_xor_sync(0xffffffffu, s, 2);
        s += __shfl_xor_sync(0xffffffffu, s, 4);
        s += __shfl_xor_sync(0xffffffffu, s, 8);
        float mean = s * (1.f / 259.f);
        float sq = 0.f;
        #pragma unroll
        for (int i = 0; i < 8; i++) {
            float d0 = xv[i] - mean, d1 = cv[i] - mean;
            sq += d0 * d0 + d1 * d1;
        }
        if (q == 0) {
            float d0 = c0 - mean, d1 = c1 - mean, d2 = c2v - mean;
            sq += d0 * d0 + d1 * d1 + d2 * d2;
        }
        sq += __shfl_xor_sync(0xffffffffu, sq, 1);
        sq += __shfl_xor_sync(0xffffffffu, sq, 2);
        sq += __shfl_xor_sync(0xffffffffu, sq, 4);
        sq += __shfl_xor_sync(0xffffffffu, sq, 8);
        float inv = rsqrtf(sq * (1.f / 259.f) + 1e-5f);

        uint32_t pk[4];
        #pragma unroll
        for (int i = 0; i < 4; i++) {
            int ca = q * 8 + 2 * i;
            pk[i] = packbf((xv[2 * i] - mean) * inv * par[PAR_LNFG + ca] + par[PAR_LNFB + ca],
                           (xv[2 * i + 1] - mean) * inv * par[PAR_LNFG + ca + 1] + par[PAR_LNFB + ca + 1]);
        }
        *(uint4*)(dsm + SM_ACT + (hb * 16 + row) * ASTR + q * 16) = *(uint4*)&pk[0];
        #pragma unroll
        for (int i = 0; i < 4; i++) {
            int ca = 128 + q * 8 + 2 * i;
            pk[i] = packbf((cv[2 * i] - mean) * inv * par[PAR_LNFG + ca] + par[PAR_LNFB + ca],
                           (cv[2 * i + 1] - mean) * inv * par[PAR_LNFG + ca + 1] + par[PAR_LNFB + ca + 1]);
        }
        *(uint4*)(dsm + SM_ACT + (hb * 16 + row) * ASTR + 256 + q * 16) = *(uint4*)&pk[0];
        if (q == 0) {
            uint32_t tp0 = packbf((c0 - mean) * inv * par[PAR_LNFG + 256] + par[PAR_LNFB + 256],
                                  (c1 - mean) * inv * par[PAR_LNFG + 257] + par[PAR_LNFB + 257]);
            uint32_t tp1 = packbf((c2v - mean) * inv * par[PAR_LNFG + 258] + par[PAR_LNFB + 258], 0.f);
            *(uint2*)(dsm + SM_ACT + (hb * 16 + row) * ASTR + 512) = make_uint2(tp0, tp1);
        } else if (q >= 2) {
            *(uint32_t*)(dsm + SM_ACT + (hb * 16 + row) * ASTR + 512 + q * 4) = 0u;
        }
    }
    barh(barid);

    // ============ stage 1: h0 = comb @ wop1 ; LN + SiLU ============
    do_gemm(SM_WOP1, 9);
    stage(par + PAR_OPB1);
    barh(barid);
    {
        float v[8];
        #pragma unroll
        for (int i = 0; i < 2; i++) {
            float4 f = *(const float4*)&sSh[row * 136 + q * 8 + i * 4];
            v[4 * i] = f.x; v[4 * i + 1] = f.y; v[4 * i + 2] = f.z; v[4 * i + 3] = f.w;
        }
        float s = 0.f;
        #pragma unroll
        for (int i = 0; i < 8; i++) s += v[i];
        s += __shfl_xor_sync(0xffffffffu, s, 1);
        s += __shfl_xor_sync(0xffffffffu, s, 2);
        s += __shfl_xor_sync(0xffffffffu, s, 4);
        s += __shfl_xor_sync(0xffffffffu, s, 8);
        float mean = s * (1.f / 128.f);
        float sq = 0.f;
        #pragma unroll
        for (int i = 0; i < 8; i++) { float d = v[i] - mean; sq += d * d; }
        sq += __shfl_xor_sync(0xffffffffu, sq, 1);
        sq += __shfl_xor_sync(0xffffffffu, sq, 2);
        sq += __shfl_xor_sync(0xffffffffu, sq, 4);
        sq += __shfl_xor_sync(0xffffffffu, sq, 8);
        float inv = rsqrtf(sq * (1.f / 128.f) + 1e-5f);
        #pragma unroll
        for (int i = 0; i < 4; i++) {
            int ca = q * 8 + 2 * i;
            float y0 = silu_f((v[2 * i] - mean) * inv * par[PAR_LN1G + ca] + par[PAR_LN1B + ca]);
            float y1 = silu_f((v[2 * i + 1] - mean) * inv * par[PAR_LN1G + ca + 1] + par[PAR_LN1B + ca + 1]);
            hkeep[i] = packbf(y0, y1);
        }
        *(uint4*)(dsm + SM_ACT + (hb * 16 + row) * ASTR + q * 16) = *(uint4*)&hkeep[0];
    }
    barh(barid);

    // ============ stage 2: t = h1 @ wr1 ; LN + SiLU ============
    do_gemm(SM_WR1, 4);
    stage(par + PAR_RB1);
    barh(barid);
    {
        float v[8];
        #pragma unroll
        for (int i = 0; i < 2; i++) {
            float4 f = *(const float4*)&sSh[row * 136 + q * 8 + i * 4];
            v[4 * i] = f.x; v[4 * i + 1] = f.y; v[4 * i + 2] = f.z; v[4 * i + 3] = f.w;
        }
        float s = 0.f;
        #pragma unroll
        for (int i = 0; i < 8; i++) s += v[i];
        s += __shfl_xor_sync(0xffffffffu, s, 1);
        s += __shfl_xor_sync(0xffffffffu, s, 2);
        s += __shfl_xor_sync(0xffffffffu, s, 4);
        s += __shfl_xor_sync(0xffffffffu, s, 8);
        float mean = s * (1.f / 128.f);
        float sq = 0.f;
        #pragma unroll
        for (int i = 0; i < 8; i++) { float d = v[i] - mean; sq += d * d; }
        sq += __shfl_xor_sync(0xffffffffu, sq, 1);
        sq += __shfl_xor_sync(0xffffffffu, sq, 2);
        sq += __shfl_xor_sync(0xffffffffu, sq, 4);
        sq += __shfl_xor_sync(0xffffffffu, sq, 8);
        float inv = rsqrtf(sq * (1.f / 128.f) + 1e-5f);
        uint32_t pk[4];
        #pragma unroll
        for (int i = 0; i < 4; i++) {
            int ca = q * 8 + 2 * i;
            float y0 = silu_f((v[2 * i] - mean) * inv * par[PAR_RLNG + ca] + par[PAR_RLNB + ca]);
            float y1 = silu_f((v[2 * i + 1] - mean) * inv * par[PAR_RLNG + ca + 1] + par[PAR_RLNB + ca + 1]);
            pk[i] = packbf(y0, y1);
        }
        *(uint4*)(dsm + SM_ACT + (hb * 16 + row) * ASTR + q * 16) = *(uint4*)&pk[0];
    }
    barh(barid);

    // ============ stage 3: hfin = t2 @ wr2 + b + h1 ; LN ; proj/tanh/clamp ============
    do_gemm(SM_WR2, 4);
    stage(par + PAR_RB2);
    barh(barid);
    {
        float v[8];
        #pragma unroll
        for (int i = 0; i < 2; i++) {
            float4 f = *(const float4*)&sSh[row * 136 + q * 8 + i * 4];
            v[4 * i] = f.x; v[4 * i + 1] = f.y; v[4 * i + 2] = f.z; v[4 * i + 3] = f.w;
        }
        #pragma unroll
        for (int i = 0; i < 4; i++) {
            __nv_bfloat162 hh = *(__nv_bfloat162*)&hkeep[i];
            v[2 * i]     += __bfloat162float(hh.x);
            v[2 * i + 1] += __bfloat162float(hh.y);
        }
        float s = 0.f;
        #pragma unroll
        for (int i = 0; i < 8; i++) s += v[i];
        s += __shfl_xor_sync(0xffffffffu, s, 1);
        s += __shfl_xor_sync(0xffffffffu, s, 2);
        s += __shfl_xor_sync(0xffffffffu, s, 4);
        s += __shfl_xor_sync(0xffffffffu, s, 8);
        float mean = s * (1.f / 128.f);
        float sq = 0.f;
        #pragma unroll
        for (int i = 0; i < 8; i++) { float d = v[i] - mean; sq += d * d; }
        sq += __shfl_xor_sync(0xffffffffu, sq, 1);
        sq += __shfl_xor_sync(0xffffffffu, sq, 2);
        sq += __shfl_xor_sync(0xffffffffu, sq, 4);
        sq += __shfl_xor_sync(0xffffffffu, sq, 8);
        float inv = rsqrtf(sq * (1.f / 128.f) + 1e-5f);

        float p0 = 0.f, p1 = 0.f, p2 = 0.f;
        #pragma unroll
        for (int i = 0; i < 8; i++) {
            int ca = q * 8 + i;
            float y = (v[i] - mean) * inv * par[PAR_LN2G + ca] + par[PAR_LN2B + ca];
            p0 += y * par[PAR_W3 + ca * 3 + 0];
            p1 += y * par[PAR_W3 + ca * 3 + 1];
            p2 += y * par[PAR_W3 + ca * 3 + 2];
        }
        #pragma unroll
        for (int off = 8; off > 0; off >>= 1) {
            p0 += __shfl_xor_sync(0xffffffffu, p0, off);
            p1 += __shfl_xor_sync(0xffffffffu, p1, off);
            p2 += __shfl_xor_sync(0xffffffffu, p2, off);
        }
        if (q == 0) {
            int bi = bidx[grow];
            float dots[3] = {p0 + par[PAR_B3 + 0], p1 + par[PAR_B3 + 1], p2 + par[PAR_B3 + 2]};
            #pragma unroll
            for (int j = 0; j < 3; j++) {
                float val = coordp[grow * 3 + j] + 0.01f * tanhf(dots[j]);
                fout[grow * 3 + j] = fminf(fmaxf(val, bmin[bi * 3 + j]), bmax[bi * 3 + j]);
            }
        }
    }
}

// ======== flash: fp8 QK, 128 q-rows/CTA (2 m-tiles/warp), KSPLIT=8, bf16 partials ========
#define QSTRIDE 48
#define VSTRIDE 80
#define QBUF    6144
#define KB8     6144
#define VB16    10240
#define KVPAIR  (KB8 + VB16)
#define NITER   (32 / KSPLIT)

__device__ __forceinline__ void kv_load128(const uint8_t* __restrict__ Kf,
                                           const __nv_bfloat16* __restrict__ Vh,
                                           int h, int kb, uint32_t sbase, int tid) {
    #pragma unroll
    for (int i = 0; i < 2; i++) {
        cpa16(sbase + tid * QSTRIDE + i * 16,
              Kf + (((h << 12) + (kb << 7) + tid) << 5) + i * 16);
    }
    #pragma unroll
    for (int i = 0; i < 4; i++) {
        cpa16(sbase + KB8 + tid * VSTRIDE + i * 16,
              Vh + (((h << 12) + (kb << 7) + tid) << 5) + i * 8);
    }
    asm volatile("cp.async.commit_group;");
}

__global__ void __launch_bounds__(128) flashb_k(const uint8_t* __restrict__ Qf,
                                                const uint8_t* __restrict__ Kf,
                                                const __nv_bfloat16* __restrict__ Vh,
                                                __nv_bfloat16* __restrict__ opart,
                                                float* __restrict__ lpart) {
    __shared__ __align__(16) char smem[QBUF + 2 * KVPAIR];
    const int tid = threadIdx.x, lane = tid & 31, warp = tid >> 5;
    const int h = blockIdx.y, qb = blockIdx.x, sp = blockIdx.z;
    const int kb0 = sp * NITER;

    uint32_t Qsa = (uint32_t)__cvta_generic_to_shared(smem);
    uint32_t kva0 = Qsa + QBUF;
    uint32_t kva1 = Qsa + QBUF + KVPAIR;

    #pragma unroll
    for (int i = 0; i < 2; i++) {
        int s = tid + i * 128;
        int row = s >> 1, seg = s & 1;
        uint4 v = *(const uint4*)(Qf + (((h << 12) + (qb << 7) + row) << 5) + seg * 16);
        *(uint4*)(smem + row * QSTRIDE + seg * 16) = v;
    }
    kv_load128(Kf, Vh, h, kb0 + 0, kva0, tid);
    kv_load128(Kf, Vh, h, kb0 + 1, kva1, tid);
    __syncthreads();

    uint32_t qa[8];
    {
        int i = lane & 7, sl = lane >> 3;
        #pragma unroll
        for (int mt = 0; mt < 2; mt++) {
            int row = warp * 32 + mt * 16 + ((sl & 1) ? 8 : 0) + i;
            uint32_t a = Qsa + row * QSTRIDE + ((sl >> 1) ? 16 : 0);
            ldsm4(qa[mt * 4 + 0], qa[mt * 4 + 1], qa[mt * 4 + 2], qa[mt * 4 + 3], a);
        }
    }

    float l00 = 0.f, l01 = 0.f, l10 = 0.f, l11 = 0.f;
    float o0[4][4], o1[4][4];
    #pragma unroll
    for (int j = 0; j < 4; j++)
        #pragma unroll
        for (int c = 0; c < 4; c++) { o0[j][c] = 0.f; o1[j][c] = 0.f; }

    const int i7 = lane & 7, sel = lane >> 3;
    const uint32_t krow = ((sel >= 2) ? 8 : 0) + i7;
    const uint32_t kcol = (sel & 1) ? 16 : 0;
    const uint32_t vrow = ((sel & 1) ? 8 : 0) + i7;
    const uint32_t vcol = (sel >= 2) ? 16 : 0;

    for (int kb = 0; kb < NITER; kb++) {
        if (kb < NITER - 1) asm volatile("cp.async.wait_group 1;");
        else                asm volatile("cp.async.wait_group 0;");
        __syncthreads();
        uint32_t Kbase = (kb & 1) ? kva1 : kva0;
        uint32_t Vbase = Kbase + KB8;

        #pragma unroll
        for (int ks = 0; ks < 8; ks++) {
            uint32_t a = Kbase + (ks * 16 + krow) * QSTRIDE + kcol;
            uint32_t b0, b1, b2, b3;
            ldsm4(b0, b1, b2, b3, a);

            float s00[4] = {0.f, 0.f, 0.f, 0.f}, s01[4] = {0.f, 0.f, 0.f, 0.f};
            float s10[4] = {0.f, 0.f, 0.f, 0.f}, s11[4] = {0.f, 0.f, 0.f, 0.f};
            mma16832(s00, qa,     b0, b1);
            mma16832(s01, qa,     b2, b3);
            mma16832(s10, qa + 4, b0, b1);
            mma16832(s11, qa + 4, b2, b3);

            uint32_t e00 = schexp(s00[0]), e01 = schexp(s00[1]);
            uint32_t e02 = schexp(s00[2]), e03 = schexp(s00[3]);
            uint32_t f00 = schexp(s01[0]), f01 = schexp(s01[1]);
            uint32_t f02 = schexp(s01[2]), f03 = schexp(s01[3]);
            uint32_t e10 = schexp(s10[0]), e11 = schexp(s10[1]);
            uint32_t e12 = schexp(s10[2]), e13 = schexp(s10[3]);
            uint32_t f10 = schexp(s11[0]), f11 = schexp(s11[1]);
            uint32_t f12 = schexp(s11[2]), f13 = schexp(s11[3]);

            l00 += (__int_as_float(e00) + __int_as_float(e01))
                 + (__int_as_float(f00) + __int_as_float(f01));
            l01 += (__int_as_float(e02) + __int_as_float(e03))
                 + (__int_as_float(f02) + __int_as_float(f03));
            l10 += (__int_as_float(e10) + __int_as_float(e11))
                 + (__int_as_float(f10) + __int_as_float(f11));
            l11 += (__int_as_float(e12) + __int_as_float(e13))
                 + (__int_as_float(f12) + __int_as_float(f13));

            uint32_t pa0[4], pa1[4];
            pa0[0] = prmt16(e00, e01); pa0[1] = prmt16(e02, e03);
            pa0[2] = prmt16(f00, f01); pa0[3] = prmt16(f02, f03);
            pa1[0] = prmt16(e10, e11); pa1[1] = prmt16(e12, e13);
            pa1[2] = prmt16(f10, f11); pa1[3] = prmt16(f12, f13);

            uint32_t av = Vbase + (ks * 16 + vrow) * VSTRIDE + vcol;
            uint32_t v0, v1, v2, v3, w0, w1, w2, w3;
            ldsm4t(v0, v1, v2, v3, av);
            ldsm4t(w0, w1, w2, w3, av + 32);
            mma16816(o0[0], pa0, v0, v1);
            mma16816(o0[1], pa0, v2, v3);
            mma16816(o0[2], pa0, w0, w1);
            mma16816(o0[3], pa0, w2, w3);
            mma16816(o1[0], pa1, v0, v1);
            mma16816(o1[1], pa1, v2, v3);
            mma16816(o1[2], pa1, w0, w1);
            mma16816(o1[3], pa1, w2, w3);
        }

        __syncthreads();
        if (kb < NITER - 2) kv_load128(Kf, Vh, h, kb0 + kb + 2, (kb & 1) ? kva1 : kva0, tid);
    }

    l00 += __shfl_xor_sync(0xffffffffu, l00, 1);
    l00 += __shfl_xor_sync(0xffffffffu, l00, 2);
    l01 += __shfl_xor_sync(0xffffffffu, l01, 1);
    l01 += __shfl_xor_sync(0xffffffffu, l01, 2);
    l10 += __shfl_xor_sync(0xffffffffu, l10, 1);
    l10 += __shfl_xor_sync(0xffffffffu, l10, 2);
    l11 += __shfl_xor_sync(0xffffffffu, l11, 1);
    l11 += __shfl_xor_sync(0xffffffffu, l11, 2);

    int g = lane >> 2, l2 = (lane & 3) * 2;
    int row0 = (qb << 7) + warp * 32 + g;
    __nv_bfloat16* op = opart + sp * NATOMS * HDIM;
    #pragma unroll
    for (int j = 0; j < 4; j++) {
        int col = (h << 5) + j * 8 + l2;
        *(uint32_t*)&op[row0 * HDIM + col]        = packbf(o0[j][0], o0[j][1]);
        *(uint32_t*)&op[(row0 + 8) * HDIM + col]  = packbf(o0[j][2], o0[j][3]);
        *(uint32_t*)&op[(row0 + 16) * HDIM + col] = packbf(o1[j][0], o1[j][1]);
        *(uint32_t*)&op[(row0 + 24) * HDIM + col] = packbf(o1[j][2], o1[j][3]);
    }
    if ((lane & 3) == 0) {
        float* lp = lpart + sp * NHEAD * NATOMS + h * NATOMS;
        lp[row0]      = l00;
        lp[row0 + 8]  = l01;
        lp[row0 + 16] = l10;
        lp[row0 + 24] = l11;
    }
}

// ---------------- host ----------------
extern "C" void kernel_launch(void* const* d_in, const int* in_sizes, int n_in,
                              void* d_out, int out_size) {
    const int*   num_atoms  = (const int*)d_in[0];
    const int*   elems      = (const int*)d_in[1];
    const float* cell       = (const float*)d_in[2];
    const float* coord      = (const float*)d_in[3];
    const float* emb        = (const float*)d_in[4];
    const float* ln_in_g    = (const float*)d_in[5];
    const float* ln_in_b    = (const float*)d_in[6];
    const float* attn_in_w  = (const float*)d_in[7];
    const float* attn_in_b  = (const float*)d_in[8];
    const float* attn_out_w = (const float*)d_in[9];
    const float* attn_out_b = (const float*)d_in[10];
    const float* ce_w1      = (const float*)d_in[11];
    const float* ce_b1      = (const float*)d_in[12];
    const float* ce_w2      = (const float*)d_in[13];
    const float* ce_b2      = (const float*)d_in[14];
    const float* ln_feat_g  = (const float*)d_in[15];
    const float* ln_feat_b  = (const float*)d_in[16];
    const float* op_w1      = (const float*)d_in[17];
    const float* op_b1      = (const float*)d_in[18];
    const float* op_ln1_g   = (const float*)d_in[19];
    const float* op_ln1_b   = (const float*)d_in[20];
    const float* res_w1     = (const float*)d_in[21];
    const float* res_b1     = (const float*)d_in[22];
    const float* res_ln_g   = (const float*)d_in[23];
    const float* res_ln_b   = (const float*)d_in[24];
    const float* res_w2     = (const float*)d_in[25];
    const float* res_b2     = (const float*)d_in[26];
    const float* op_ln2_g   = (const float*)d_in[27];
    const float* op_ln2_b   = (const float*)d_in[28];
    const float* op_w3      = (const float*)d_in[29];
    const float* op_b3      = (const float*)d_in[30];
    float* out = (float*)d_out;

    float* S = nullptr;
    cudaGetSymbolAddress((void**)&S, g_scratch);
    int* bidx = nullptr;
    cudaGetSymbolAddress((void**)&bidx, g_bidx);

    __nv_bfloat16* P = (__nv_bfloat16*)S;
    __nv_bfloat16* xb    = P; P += NATOMS * HDIM;
    __nv_bfloat16* Vh    = P; P += NATOMS * HDIM;
    __nv_bfloat16* wqkv  = P; P += 128 * 384;
    __nv_bfloat16* wao   = P; P += 128 * 128;
    __nv_bfloat16* wop1  = P; P += FPAD * 128;
    __nv_bfloat16* wr1   = P; P += 128 * 128;
    __nv_bfloat16* wr2   = P; P += 128 * 128;
    __nv_bfloat16* opart = P; P += KSPLIT * NATOMS * HDIM;
    uint8_t* U = (uint8_t*)P;
    uint8_t* Qf = U; U += NATOMS * HDIM;
    uint8_t* Kf = U; U += NATOMS * HDIM;
    U = (uint8_t*)(((uintptr_t)U + 15) & ~(uintptr_t)15);
    float* F = (float*)U;
    float* lpart = F; F += KSPLIT * NHEAD * NATOMS;
    float* cf    = F; F += BATCH * HDIM;
    float* bmin  = F; F += BATCH * 3;
    float* bmax  = F; F += BATCH * 3;

    static bool attr_set = false;
    if (!attr_set) {
        cudaFuncSetAttribute(tail_k, cudaFuncAttributeMaxDynamicSharedMemorySize, SMEM_TAIL);
        attr_set = true;
    }

    setup_k<<<1049, 256>>>(elems, emb, ln_in_g, ln_in_b, xb,
                           attn_in_w, attn_out_w, op_w1, res_w1, res_w2,
                           wqkv, wao, wop1, wr1, wr2,
                           cell, ce_w1, ce_b1, ce_w2, ce_b2, cf,
                           num_atoms, bmin, bmax);

    qkv_k<<<dim3(3, 128), 128>>>(xb, wqkv, attn_in_b, Qf, Kf, Vh);

    flashb_k<<<dim3(32, NHEAD, KSPLIT), 128>>>(Qf, Kf, Vh, opart, lpart);

    tail_k<<<128, 512, SMEM_TAIL>>>(opart, lpart,
        wao, attn_out_b, ln_feat_g, ln_feat_b, cf, coord, bidx,
        wop1, op_b1, op_ln1_g, op_ln1_b,
        wr1, res_b1, res_ln_g, res_ln_b,
        wr2, res_b2, op_ln2_g, op_ln2_b,
        op_w3, op_b3, bmin, bmax, out);
}